// round 6
// baseline (speedup 1.0000x reference)
#include <cuda_runtime.h>

#define BB 64
#define HH 14
#define WWD 14
#define HW 196
#define CC 32
#define OO 10
#define NCH 14              // hw-chunks per batch (passes 1/2)
#define HWB (HW/NCH)        // 14 hw positions per block
#define TPB 320             // 10 warps: warp = o, lane = c
#define EPSF 1e-9f
#define LOG2PI 1.8378770664093453f

typedef unsigned long long u64;

// ---- f32x2 packed math (Blackwell) ---------------------------------------
__device__ __forceinline__ u64 pack2(float lo, float hi) {
    u64 r; asm("mov.b64 %0, {%1,%2};" : "=l"(r) : "f"(lo), "f"(hi)); return r;
}
__device__ __forceinline__ u64 pdup(float x) { return pack2(x, x); }
__device__ __forceinline__ void unpack2(u64 v, float& lo, float& hi) {
    asm("mov.b64 {%0,%1}, %2;" : "=f"(lo), "=f"(hi) : "l"(v));
}
__device__ __forceinline__ u64 fma2(u64 a, u64 b, u64 c) {
    u64 d; asm("fma.rn.f32x2 %0,%1,%2,%3;" : "=l"(d) : "l"(a), "l"(b), "l"(c)); return d;
}
__device__ __forceinline__ u64 mul2(u64 a, u64 b) {
    u64 d; asm("mul.rn.f32x2 %0,%1,%2;" : "=l"(d) : "l"(a), "l"(b)); return d;
}
__device__ __forceinline__ u64 add2(u64 a, u64 b) {
    u64 d; asm("add.rn.f32x2 %0,%1,%2;" : "=l"(d) : "l"(a), "l"(b)); return d;
}

// Scratch (fully rewritten every pass -> deterministic, graph-safe)
__device__ float g_partials[BB*NCH*OO*33]; // [b][chunk][o][S0,S1[16],S2[16]]
__device__ float g_params[BB*OO*33];       // [b][o][K, ivar[16], muinv[16]]
__device__ int   g_count[BB];              // arrival counters (winner resets)

// ===========================================================================
// PASS 0 via moments. rr = 1/O is o-independent, so
//   S1[o,d] = sum_n a*v,  S2[o,d] = sum_n a*v^2
// factor through per-(b,c) moments of (a, p). One block per batch b.
// Moment layout per c (69 floats):
//   [0]      m0   = sum a
//   [1..16]  m1_j = sum a*p_j
//   [17..56] M_i[jk] (j<=k sym, 10 per i-block) = sum a*p_{i4+j}*p_{i4+k}
//   [57] mw  [58] mh  [59] mw2  [60] mh2
//   [61..64] mwp_j = sum a*ow*p_{0j}   [65..68] mhp_j = sum a*oh*p_{4+j}
// ===========================================================================
__global__ void __launch_bounds__(512)
caps_pass0(const float* __restrict__ pose,
           const float* __restrict__ act,
           const float* __restrict__ w,
           const float* __restrict__ beta_a,
           const float* __restrict__ beta_u)
{
    __shared__ float mom[CC][70];

    const int b   = blockIdx.x;
    const int tid = threadIdx.x;
    const int c   = tid >> 4;      // 0..31
    const int g   = tid & 15;      // 0..15  (hw strider)

    float A[69];
    #pragma unroll
    for (int m = 0; m < 69; m++) A[m] = 0.f;

    for (int hw = g; hw < HW; hw += 16) {
        const float* pp = pose + ((size_t)(b * HW + hw) * CC + c) * 16;
        float p[16];
        #pragma unroll
        for (int q = 0; q < 4; q++) {
            float4 t4 = ((const float4*)pp)[q];
            p[q*4+0] = t4.x; p[q*4+1] = t4.y; p[q*4+2] = t4.z; p[q*4+3] = t4.w;
        }
        const float a = act[(size_t)(b * HW + hw) * CC + c];
        const int h    = hw / WWD;
        const int wpos = hw - h * WWD;
        const float ow = (wpos + 0.5f) * (1.0f / WWD);
        const float oh = (h    + 0.5f) * (1.0f / HH);

        float ap[16];
        #pragma unroll
        for (int j = 0; j < 16; j++) ap[j] = a * p[j];

        A[0] += a;
        #pragma unroll
        for (int j = 0; j < 16; j++) A[1 + j] += ap[j];
        #pragma unroll
        for (int i = 0; i < 4; i++) {
            const int mb = 17 + i * 10;
            const int pb = i * 4;
            int idx = 0;
            #pragma unroll
            for (int j = 0; j < 4; j++)
                #pragma unroll
                for (int k = j; k < 4; k++)
                    A[mb + (idx++)] += ap[pb + j] * p[pb + k];
        }
        const float aw = a * ow, ah = a * oh;
        A[57] += aw; A[58] += ah;
        A[59] += aw * ow; A[60] += ah * oh;
        #pragma unroll
        for (int j = 0; j < 4; j++) {
            A[61 + j] += aw * p[j];
            A[65 + j] += ah * p[4 + j];
        }
    }

    // reduce over g (16-lane subgroup, xor bits 0..3 stay in-group)
    #pragma unroll
    for (int m = 0; m < 69; m++) {
        #pragma unroll
        for (int off = 8; off > 0; off >>= 1)
            A[m] += __shfl_xor_sync(0xFFFFFFFFu, A[m], off);
    }
    if (g == 0) {
        #pragma unroll
        for (int m = 0; m < 69; m++) mom[c][m] = A[m];
    }
    __syncthreads();

    // ---- combine: per (o,d) assemble S1/S2 over c, then routing params ----
    if (tid < OO * 16) {
        const int o   = tid >> 4;
        const int d   = tid & 15;
        const int i   = d >> 2;
        const int col = d & 3;

        float R0 = 0.f, S1 = 0.f, S2 = 0.f;
        for (int cc = 0; cc < CC; cc++) {
            const float* mc = mom[cc];
            const float* wc = w + ((size_t)(cc * OO + o) * 16) + col;
            const float w0 = wc[0], w1 = wc[4], w2 = wc[8], w3 = wc[12];
            R0 += mc[0];
            const float* m1 = mc + 1 + i * 4;
            S1 += m1[0]*w0 + m1[1]*w1 + m1[2]*w2 + m1[3]*w3;
            const float* M = mc + 17 + i * 10;
            S2 += w0*w0*M[0] + w1*w1*M[4] + w2*w2*M[7] + w3*w3*M[9]
                + 2.f*(w0*w1*M[1] + w0*w2*M[2] + w0*w3*M[3]
                     + w1*w2*M[5] + w1*w3*M[6] + w2*w3*M[8]);
            if (d == 3) {
                S1 += mc[57];
                S2 += mc[59] + 2.f*(mc[61]*w0 + mc[62]*w1 + mc[63]*w2 + mc[64]*w3);
            }
            if (d == 7) {
                S1 += mc[58];
                S2 += mc[60] + 2.f*(mc[65]*w0 + mc[66]*w1 + mc[67]*w2 + mc[68]*w3);
            }
        }
        // rr = 1/O scaling
        const float rs     = 0.1f * R0 + EPSF;
        const float inv_rs = 1.0f / rs;
        const float mu     = 0.1f * S1 * inv_rs;
        const float var    = fmaxf(0.1f * S2 * inv_rs - mu * mu, 0.0f) + EPSF;
        const float lv     = __logf(var);
        const float ivar   = 1.0f / var;
        const float muinv  = mu * ivar;
        const float mive   = mu * muinv;

        float sumlv = lv, summive = mive;
        #pragma unroll
        for (int off = 1; off < 16; off <<= 1) {
            sumlv   += __shfl_xor_sync(0xFFFFFFFFu, sumlv,   off);
            summive += __shfl_xor_sync(0xFFFFFFFFu, summive, off);
        }

        const float cost = rs * (16.0f * beta_u[o] + 0.5f * sumlv);
        const float x    = 1.0f * (beta_a[o] - cost);            // inv_temp = 1
        const float actv = 1.0f / (1.0f + __expf(-x));

        float* pp = g_params + (size_t)(b * OO + o) * 33;
        pp[1 + d]  = ivar;
        pp[17 + d] = muinv;
        if (d == 0)
            pp[0] = __logf(actv + EPSF)
                  - 0.5f * (16.0f * LOG2PI + sumlv)
                  - 0.5f * summive;
    }
}

// ===========================================================================
// Passes 1/2: softmax-weighted accumulate + fused winner reduce.
// grid=(NCH,BB), block=320, 3 blocks/SM. Votes recomputed after softmax to
// keep the register file at 64/thread.
// ===========================================================================
template<int FINAL>
__global__ void __launch_bounds__(TPB, 3)
caps_em(const float* __restrict__ pose,
        const float* __restrict__ act,
        const float* __restrict__ w,
        const float* __restrict__ beta_a,
        const float* __restrict__ beta_u,
        float inv_temp,
        float* __restrict__ out)
{
    __shared__ float4 sp4[HWB][CC][5];   // pose rows as float4, 80B stride
    __shared__ float  sa[HWB][CC];
    __shared__ float  ss[CC][11];
    __shared__ float  se[CC][11];
    __shared__ float4 prm[OO][8];        // (iv2k, iv2k+1, mi2k, mi2k+1)
    __shared__ float  Ksm[OO];
    __shared__ int    s_win;

    const int b   = blockIdx.y;
    const int ch  = blockIdx.x;
    const int hw0 = ch * HWB;
    const int tid = threadIdx.x;
    const int o   = tid >> 5;
    const int c   = tid & 31;

    {
        const float4* src4 = (const float4*)(pose + (size_t)(b * HW + hw0) * CC * 16);
        for (int idx = tid; idx < HWB * CC * 4; idx += TPB) {
            int t_l = idx >> 7;
            int rem = idx & 127;
            sp4[t_l][rem >> 2][rem & 3] = src4[idx];
        }
        const float* asrc = act + (size_t)(b * HW + hw0) * CC;
        for (int idx = tid; idx < HWB * CC; idx += TPB)
            sa[idx >> 5][idx & 31] = asrc[idx];
        if (tid < OO * 8) {
            const int po = tid >> 3, pk = tid & 7;
            const float* pp = g_params + (size_t)(b * OO + po) * 33;
            prm[po][pk] = make_float4(pp[1 + 2*pk], pp[2 + 2*pk],
                                      pp[17 + 2*pk], pp[18 + 2*pk]);
        }
        if (tid < OO) Ksm[tid] = g_params[(size_t)(b * OO + tid) * 33];
    }

    // per-thread w[c][o], rows packed as f32x2 column pairs
    u64 wv[4][2];
    {
        const float4* wp = (const float4*)(w + (size_t)(c * OO + o) * 16);
        #pragma unroll
        for (int j = 0; j < 4; j++) {
            float4 r = wp[j];
            wv[j][0] = pack2(r.x, r.y);
            wv[j][1] = pack2(r.z, r.w);
        }
    }

    float S0 = 0.f;
    u64 S1[8], S2[8];
    #pragma unroll
    for (int k = 0; k < 8; k++) { S1[k] = 0ull; S2[k] = 0ull; }

    __syncthreads();
    const float K = Ksm[o];

    for (int t = 0; t < HWB; t++) {
        const int hw   = hw0 + t;
        const int h    = hw / WWD;
        const int wpos = hw - h * WWD;
        const float ow = (wpos + 0.5f) * (1.0f / WWD);
        const float oh = (h    + 0.5f) * (1.0f / HH);
        const float a  = sa[t][c];

        // ---- logits (votes transient, discarded per i-block) -------------
        u64 e1 = 0ull, e2 = 0ull;
        #pragma unroll
        for (int i = 0; i < 4; i++) {
            const float4 P = sp4[t][c][i];
            const u64 p0 = pdup(P.x), p1 = pdup(P.y), p2 = pdup(P.z), p3 = pdup(P.w);
            u64 va = fma2(p0, wv[0][0], fma2(p1, wv[1][0],
                     fma2(p2, wv[2][0], mul2(p3, wv[3][0]))));
            u64 vb = fma2(p0, wv[0][1], fma2(p1, wv[1][1],
                     fma2(p2, wv[2][1], mul2(p3, wv[3][1]))));
            if (i == 0) vb = add2(vb, pack2(0.f, ow));
            if (i == 1) vb = add2(vb, pack2(0.f, oh));
            const longlong2 qa = *(const longlong2*)&prm[o][2*i];
            const longlong2 qb = *(const longlong2*)&prm[o][2*i+1];
            e1 = fma2(mul2(va, va), (u64)qa.x, e1);
            e2 = fma2(va, (u64)qa.y, e2);
            e1 = fma2(mul2(vb, vb), (u64)qb.x, e1);
            e2 = fma2(vb, (u64)qb.y, e2);
        }
        float e1l, e1h, e2l, e2h;
        unpack2(e1, e1l, e1h);
        unpack2(e2, e2l, e2h);
        const float s = fmaf(-0.5f, e1l + e1h, K + e2l + e2h);

        ss[c][o] = s;
        __syncthreads();
        float mx = ss[c][0];
        #pragma unroll
        for (int oo = 1; oo < OO; oo++) mx = fmaxf(mx, ss[c][oo]);
        const float e = __expf(s - mx);
        se[c][o] = e;
        __syncthreads();
        float den = se[c][0];
        #pragma unroll
        for (int oo = 1; oo < OO; oo++) den += se[c][oo];
        const float ap = a * __fdividef(e, den);

        // ---- recompute votes, accumulate ---------------------------------
        S0 += ap;
        const u64 ap2 = pdup(ap);
        #pragma unroll
        for (int i = 0; i < 4; i++) {
            const float4 P = sp4[t][c][i];
            const u64 p0 = pdup(P.x), p1 = pdup(P.y), p2 = pdup(P.z), p3 = pdup(P.w);
            u64 va = fma2(p0, wv[0][0], fma2(p1, wv[1][0],
                     fma2(p2, wv[2][0], mul2(p3, wv[3][0]))));
            u64 vb = fma2(p0, wv[0][1], fma2(p1, wv[1][1],
                     fma2(p2, wv[2][1], mul2(p3, wv[3][1]))));
            if (i == 0) vb = add2(vb, pack2(0.f, ow));
            if (i == 1) vb = add2(vb, pack2(0.f, oh));
            u64 t1 = mul2(ap2, va);
            S1[2*i]   = add2(S1[2*i], t1);
            S2[2*i]   = fma2(t1, va, S2[2*i]);
            u64 t2 = mul2(ap2, vb);
            S1[2*i+1] = add2(S1[2*i+1], t2);
            S2[2*i+1] = fma2(t2, vb, S2[2*i+1]);
        }
    }

    // ---- reduce over 32 c's ----------------------------------------------
    #pragma unroll
    for (int off = 16; off > 0; off >>= 1) {
        S0 += __shfl_xor_sync(0xFFFFFFFFu, S0, off);
        #pragma unroll
        for (int k = 0; k < 8; k++) {
            u64 a1 = __shfl_xor_sync(0xFFFFFFFFu, S1[k], off);
            u64 a2 = __shfl_xor_sync(0xFFFFFFFFu, S2[k], off);
            S1[k] = add2(S1[k], a1);
            S2[k] = add2(S2[k], a2);
        }
    }
    if (c == 0) {
        float* dst = g_partials + (size_t)((b * NCH + ch) * OO + o) * 33;
        dst[0] = S0;
        #pragma unroll
        for (int k = 0; k < 8; k++) {
            float lo, hi;
            unpack2(S1[k], lo, hi);
            dst[1 + 2*k] = lo;  dst[2 + 2*k] = hi;
            unpack2(S2[k], lo, hi);
            dst[17 + 2*k] = lo; dst[18 + 2*k] = hi;
        }
    }

    // ---- winner block per batch does the reduce --------------------------
    __syncthreads();
    if (tid == 0) {
        __threadfence();
        int prev = atomicAdd(&g_count[b], 1);
        s_win = (prev == NCH - 1);
    }
    __syncthreads();
    if (!s_win) return;
    __threadfence();

    if (tid < OO * 16) {
        const int ro = tid >> 4;
        const int rd = tid & 15;

        float R0 = 0.f, R1 = 0.f, R2 = 0.f;
        #pragma unroll 2
        for (int g = 0; g < NCH; g++) {
            const float* p = g_partials + (size_t)((b * NCH + g) * OO + ro) * 33;
            R0 += p[0];
            R1 += p[1 + rd];
            R2 += p[17 + rd];
        }

        const float rs     = R0 + EPSF;
        const float inv_rs = 1.0f / rs;
        const float mu     = R1 * inv_rs;
        const float var    = fmaxf(R2 * inv_rs - mu * mu, 0.0f) + EPSF;
        const float lv     = __logf(var);
        const float ivar   = 1.0f / var;
        const float muinv  = mu * ivar;
        const float mive   = mu * muinv;

        float sumlv = lv, summive = mive;
        #pragma unroll
        for (int off = 1; off < 16; off <<= 1) {
            sumlv   += __shfl_xor_sync(0xFFFFFFFFu, sumlv,   off);
            summive += __shfl_xor_sync(0xFFFFFFFFu, summive, off);
        }

        const float cost = rs * (16.0f * beta_u[ro] + 0.5f * sumlv);
        const float x    = inv_temp * (beta_a[ro] - cost);
        const float actv = 1.0f / (1.0f + __expf(-x));

        if (FINAL) {
            out[(size_t)(b * OO + ro) * 16 + rd] = mu;
            if (rd == 0) out[BB * OO * 16 + b * OO + ro] = actv;
        } else {
            float* pp = g_params + (size_t)(b * OO + ro) * 33;
            pp[1 + rd]  = ivar;
            pp[17 + rd] = muinv;
            if (rd == 0)
                pp[0] = __logf(actv + EPSF)
                      - 0.5f * (16.0f * LOG2PI + sumlv)
                      - 0.5f * summive;
        }
    }
    if (tid == 0) g_count[b] = 0;
}

// ---------------------------------------------------------------------------
extern "C" void kernel_launch(void* const* d_in, const int* in_sizes, int n_in,
                              void* d_out, int out_size)
{
    const float* pose = (const float*)d_in[0];
    const float* act  = (const float*)d_in[1];
    const float* w    = (const float*)d_in[2];
    const float* ba   = (const float*)d_in[3];
    const float* bu   = (const float*)d_in[4];
    float* out = (float*)d_out;

    dim3 ga(NCH, BB);

    caps_pass0<<<BB, 512>>>(pose, act, w, ba, bu);                 // it=0 via moments
    caps_em<0><<<ga, TPB>>>(pose, act, w, ba, bu, 2.0f, out);      // it=1
    caps_em<1><<<ga, TPB>>>(pose, act, w, ba, bu, 3.0f, out);      // it=2 -> outputs
}

// round 11
// speedup vs baseline: 1.3005x; 1.3005x over previous
#include <cuda_runtime.h>

#define BB 64
#define HH 14
#define WWD 14
#define HW 196
#define CC 32
#define OO 10
#define NCH 14              // hw-chunks per batch (passes 1/2)
#define HWB (HW/NCH)        // 14 hw positions per block
#define TPB 320             // 10 warps: warp = o, lane = c
#define PCH 4               // pass0 hw-chunks per batch
#define PHW (HW/PCH)        // 49
#define EPSF 1e-9f
#define LOG2PI 1.8378770664093453f

typedef unsigned long long u64;

// ---- f32x2 packed math (Blackwell) ---------------------------------------
__device__ __forceinline__ u64 pack2(float lo, float hi) {
    u64 r; asm("mov.b64 %0, {%1,%2};" : "=l"(r) : "f"(lo), "f"(hi)); return r;
}
__device__ __forceinline__ u64 pdup(float x) { return pack2(x, x); }
__device__ __forceinline__ void unpack2(u64 v, float& lo, float& hi) {
    asm("mov.b64 {%0,%1}, %2;" : "=f"(lo), "=f"(hi) : "l"(v));
}
__device__ __forceinline__ u64 fma2(u64 a, u64 b, u64 c) {
    u64 d; asm("fma.rn.f32x2 %0,%1,%2,%3;" : "=l"(d) : "l"(a), "l"(b), "l"(c)); return d;
}
__device__ __forceinline__ u64 mul2(u64 a, u64 b) {
    u64 d; asm("mul.rn.f32x2 %0,%1,%2;" : "=l"(d) : "l"(a), "l"(b)); return d;
}
__device__ __forceinline__ u64 add2(u64 a, u64 b) {
    u64 d; asm("add.rn.f32x2 %0,%1,%2;" : "=l"(d) : "l"(a), "l"(b)); return d;
}

// Scratch (fully rewritten every pass -> deterministic, graph-safe)
__device__ float g_partials[BB*NCH*OO*33]; // [b][chunk][o][S0,S1[16],S2[16]]
__device__ float g_params[BB*OO*33];       // [b][o][K, ivar[16], muinv[16]]
__device__ float g_mom[BB*PCH*CC*70];      // pass0 partial moments
__device__ int   g_count[BB];              // em-pass counters (winner resets)
__device__ int   g_cnt0[BB];               // pass0 counters (winner resets)

// ===========================================================================
// PASS 0 via moments (rr = 1/O is o-independent).
// grid=(PCH, BB), block=512: c = tid>>4 (32), g = tid&15 (hw strider).
// Moment layout per c (69): [0]=sum a; [1..16]=sum a*p_j;
// [17..56] sym 4x4 per i-block (10 each); [57]aw [58]ah [59]aw2 [60]ah2;
// [61..64] a*ow*p_{0..3}; [65..68] a*oh*p_{4..7}.
// Last block per b: sum chunk moments, assemble S1/S2 per (o,d), write params.
// ===========================================================================
__global__ void __launch_bounds__(512)
caps_pass0(const float* __restrict__ pose,
           const float* __restrict__ act,
           const float* __restrict__ w,
           const float* __restrict__ beta_a,
           const float* __restrict__ beta_u)
{
    __shared__ float mom[CC][70];
    __shared__ int   s_win;

    const int ch  = blockIdx.x;
    const int b   = blockIdx.y;
    const int tid = threadIdx.x;
    const int c   = tid >> 4;
    const int g   = tid & 15;

    float A[69];
    #pragma unroll
    for (int m = 0; m < 69; m++) A[m] = 0.f;

    for (int hwl = g; hwl < PHW; hwl += 16) {
        const int hw = ch * PHW + hwl;
        const float* pp = pose + ((size_t)(b * HW + hw) * CC + c) * 16;
        float p[16];
        #pragma unroll
        for (int q = 0; q < 4; q++) {
            float4 t4 = ((const float4*)pp)[q];
            p[q*4+0] = t4.x; p[q*4+1] = t4.y; p[q*4+2] = t4.z; p[q*4+3] = t4.w;
        }
        const float a = act[(size_t)(b * HW + hw) * CC + c];
        const int h    = hw / WWD;
        const int wpos = hw - h * WWD;
        const float ow = (wpos + 0.5f) * (1.0f / WWD);
        const float oh = (h    + 0.5f) * (1.0f / HH);

        float ap[16];
        #pragma unroll
        for (int j = 0; j < 16; j++) ap[j] = a * p[j];

        A[0] += a;
        #pragma unroll
        for (int j = 0; j < 16; j++) A[1 + j] += ap[j];
        #pragma unroll
        for (int i = 0; i < 4; i++) {
            const int mb = 17 + i * 10;
            const int pb = i * 4;
            int idx = 0;
            #pragma unroll
            for (int j = 0; j < 4; j++)
                #pragma unroll
                for (int k = j; k < 4; k++)
                    A[mb + (idx++)] += ap[pb + j] * p[pb + k];
        }
        const float aw = a * ow, ah = a * oh;
        A[57] += aw; A[58] += ah;
        A[59] += aw * ow; A[60] += ah * oh;
        #pragma unroll
        for (int j = 0; j < 4; j++) {
            A[61 + j] += aw * p[j];
            A[65 + j] += ah * p[4 + j];
        }
    }

    // reduce over 16-lane g-group (xor bits 0..3 stay in-group)
    #pragma unroll
    for (int m = 0; m < 69; m++) {
        #pragma unroll
        for (int off = 8; off > 0; off >>= 1)
            A[m] += __shfl_xor_sync(0xFFFFFFFFu, A[m], off);
    }
    if (g == 0) {
        float* dst = g_mom + (size_t)((b * PCH + ch) * CC + c) * 70;
        #pragma unroll
        for (int m = 0; m < 69; m++) dst[m] = A[m];
    }

    // ---- winner block per batch combines ----------------------------------
    __syncthreads();
    if (tid == 0) {
        __threadfence();
        int prev = atomicAdd(&g_cnt0[b], 1);
        s_win = (prev == PCH - 1);
    }
    __syncthreads();
    if (!s_win) return;
    __threadfence();

    for (int idx = tid; idx < CC * 69; idx += 512) {
        const int cc = idx / 69;
        const int m  = idx - cc * 69;
        float s = 0.f;
        #pragma unroll
        for (int gch = 0; gch < PCH; gch++)
            s += g_mom[(size_t)((b * PCH + gch) * CC + cc) * 70 + m];
        mom[cc][m] = s;
    }
    __syncthreads();

    if (tid < OO * 16) {
        const int o   = tid >> 4;
        const int d   = tid & 15;
        const int i   = d >> 2;
        const int col = d & 3;

        float R0 = 0.f, S1 = 0.f, S2 = 0.f;
        for (int cc = 0; cc < CC; cc++) {
            const float* mc = mom[cc];
            const float* wc = w + ((size_t)(cc * OO + o) * 16) + col;
            const float w0 = wc[0], w1 = wc[4], w2 = wc[8], w3 = wc[12];
            R0 += mc[0];
            const float* m1 = mc + 1 + i * 4;
            S1 += m1[0]*w0 + m1[1]*w1 + m1[2]*w2 + m1[3]*w3;
            const float* M = mc + 17 + i * 10;
            S2 += w0*w0*M[0] + w1*w1*M[4] + w2*w2*M[7] + w3*w3*M[9]
                + 2.f*(w0*w1*M[1] + w0*w2*M[2] + w0*w3*M[3]
                     + w1*w2*M[5] + w1*w3*M[6] + w2*w3*M[8]);
            if (d == 3) {
                S1 += mc[57];
                S2 += mc[59] + 2.f*(mc[61]*w0 + mc[62]*w1 + mc[63]*w2 + mc[64]*w3);
            }
            if (d == 7) {
                S1 += mc[58];
                S2 += mc[60] + 2.f*(mc[65]*w0 + mc[66]*w1 + mc[67]*w2 + mc[68]*w3);
            }
        }
        const float rs     = 0.1f * R0 + EPSF;
        const float inv_rs = 1.0f / rs;
        const float mu     = 0.1f * S1 * inv_rs;
        const float var    = fmaxf(0.1f * S2 * inv_rs - mu * mu, 0.0f) + EPSF;
        const float lv     = __logf(var);
        const float ivar   = 1.0f / var;
        const float muinv  = mu * ivar;
        const float mive   = mu * muinv;

        float sumlv = lv, summive = mive;
        #pragma unroll
        for (int off = 1; off < 16; off <<= 1) {
            sumlv   += __shfl_xor_sync(0xFFFFFFFFu, sumlv,   off);
            summive += __shfl_xor_sync(0xFFFFFFFFu, summive, off);
        }

        const float cost = rs * (16.0f * beta_u[o] + 0.5f * sumlv);
        const float actv = 1.0f / (1.0f + __expf(-(beta_a[o] - cost))); // inv_temp=1

        float* pp = g_params + (size_t)(b * OO + o) * 33;
        pp[1 + d]  = ivar;
        pp[17 + d] = muinv;
        if (d == 0)
            pp[0] = __logf(actv + EPSF)
                  - 0.5f * (16.0f * LOG2PI + sumlv)
                  - 0.5f * summive;
    }
    if (tid == 0) g_cnt0[b] = 0;
}

// ===========================================================================
// Passes 1/2. Pair index sk = ip*4+k, ip in {0,1}:
//   pair sk holds d_lo = 8*ip+k (row i=2ip), d_hi = 8*ip+4+k (row i=2ip+1).
//   v[sk] = sum_j Ppair[ip][j] * dup(w[j][k]),  Ppair pre-packed in smem.
// Dynamic smem layout (u64 base):
//   sp   : u64[HWB*32*18]  (pairs, row stride 18 u64 = 144B, 16B aligned)
//   prm  : float4[OO*8]    (iv_lo, iv_hi, mi_lo, mi_hi per pair)
//   sa   : float[HWB*32]
//   ss,se: float[32*11]
//   Ksm  : float[OO]; s_win : int
// ===========================================================================
#define SP_U64   (HWB*32*18)
#define SMEM_EM  (SP_U64*8 + OO*8*16 + HWB*32*4 + 32*11*4*2 + OO*4 + 16)

template<int FINAL>
__global__ void __launch_bounds__(TPB, 2)
caps_em(const float* __restrict__ pose,
        const float* __restrict__ act,
        const float* __restrict__ w,
        const float* __restrict__ beta_a,
        const float* __restrict__ beta_u,
        float inv_temp,
        float* __restrict__ out)
{
    extern __shared__ u64 smem[];
    u64*    sp   = smem;                               // pose pairs
    float4* prm  = (float4*)(sp + SP_U64);             // OO*8
    float*  sa   = (float*)(prm + OO*8);               // HWB*32
    float*  ss   = sa + HWB*32;                        // 32*11
    float*  se   = ss + 32*11;
    float*  Ksm  = se + 32*11;                         // OO
    int*    swin = (int*)(Ksm + OO);

    const int b   = blockIdx.y;
    const int ch  = blockIdx.x;
    const int hw0 = ch * HWB;
    const int tid = threadIdx.x;
    const int o   = tid >> 5;
    const int c   = tid & 31;

    // ---- prologue: pack pose pairs, load act + params --------------------
    {
        for (int idx = tid; idx < HWB * 32 * 2; idx += TPB) {
            const int ip   = idx & 1;
            const int cell = idx >> 1;
            const int t_l  = cell >> 5;
            const int c_l  = cell & 31;
            const float4* q = (const float4*)(pose +
                ((size_t)(b * HW + hw0 + t_l) * CC + c_l) * 16) + 2 * ip;
            const float4 f0 = q[0];   // p[8ip .. 8ip+3]   (row i=2ip)
            const float4 f1 = q[1];   // p[8ip+4 .. 8ip+7] (row i=2ip+1)
            u64* dst = sp + (size_t)cell * 18 + ip * 4;
            dst[0] = pack2(f0.x, f1.x);
            dst[1] = pack2(f0.y, f1.y);
            dst[2] = pack2(f0.z, f1.z);
            dst[3] = pack2(f0.w, f1.w);
        }
        const float* asrc = act + (size_t)(b * HW + hw0) * CC;
        for (int idx = tid; idx < HWB * 32; idx += TPB)
            sa[idx] = asrc[idx];
        if (tid < OO * 8) {
            const int po = tid >> 3, pk = tid & 7;
            const int ip = pk >> 2, k = pk & 3;
            const int dlo = 8 * ip + k, dhi = dlo + 4;
            const float* pp = g_params + (size_t)(b * OO + po) * 33;
            prm[po * 8 + pk] = make_float4(pp[1 + dlo], pp[1 + dhi],
                                           pp[17 + dlo], pp[17 + dhi]);
        }
        if (tid < OO) Ksm[tid] = g_params[(size_t)(b * OO + tid) * 33];
    }

    // ---- per-thread constants: duplicated w (t-invariant) ----------------
    u64 wd[4][4];   // wd[j][k] = dup(w[c][o][j][k])
    {
        const float4* wp = (const float4*)(w + (size_t)(c * OO + o) * 16);
        #pragma unroll
        for (int j = 0; j < 4; j++) {
            const float4 r = wp[j];
            wd[j][0] = pdup(r.x); wd[j][1] = pdup(r.y);
            wd[j][2] = pdup(r.z); wd[j][3] = pdup(r.w);
        }
    }

    float S0 = 0.f;
    u64 S1[8], S2[8];
    #pragma unroll
    for (int k = 0; k < 8; k++) { S1[k] = 0ull; S2[k] = 0ull; }

    __syncthreads();
    const float K = Ksm[o];

    for (int t = 0; t < HWB; t++) {
        const int hw   = hw0 + t;
        const int h    = hw / WWD;
        const int wpos = hw - h * WWD;
        const float a  = sa[t * 32 + c];

        // pose pairs: 4x LDS.128 (16B-aligned, conflict-free per 16-lane phase)
        const u64* row = sp + (size_t)(t * 32 + c) * 18;
        const longlong2 l0 = ((const longlong2*)row)[0];  // P0[0], P0[1]
        const longlong2 l1 = ((const longlong2*)row)[1];  // P0[2], P0[3]
        const longlong2 l2 = ((const longlong2*)row)[2];  // P1[0], P1[1]
        const longlong2 l3 = ((const longlong2*)row)[3];  // P1[2], P1[3]

        u64 v[8];
        #pragma unroll
        for (int k = 0; k < 4; k++) {
            v[k]   = fma2((u64)l0.x, wd[0][k], fma2((u64)l0.y, wd[1][k],
                     fma2((u64)l1.x, wd[2][k], mul2((u64)l1.y, wd[3][k]))));
            v[4+k] = fma2((u64)l2.x, wd[0][k], fma2((u64)l2.y, wd[1][k],
                     fma2((u64)l3.x, wd[2][k], mul2((u64)l3.y, wd[3][k]))));
        }
        // coord add: d=3 = pair0 k=3 lo, d=7 = pair0 k=3 hi
        v[3] = add2(v[3], pack2((wpos + 0.5f) * (1.0f / WWD),
                                (h    + 0.5f) * (1.0f / HH)));

        // logits
        u64 e1 = 0ull, e2 = 0ull;
        #pragma unroll
        for (int k = 0; k < 8; k++) {
            const longlong2 q = *(const longlong2*)&prm[o * 8 + k]; // uniform
            e1 = fma2(mul2(v[k], v[k]), (u64)q.x, e1);
            e2 = fma2(v[k], (u64)q.y, e2);
        }
        float e1l, e1h, e2l, e2h;
        unpack2(e1, e1l, e1h);
        unpack2(e2, e2l, e2h);
        const float s = fmaf(-0.5f, e1l + e1h, K + e2l + e2h);

        ss[c * 11 + o] = s;
        __syncthreads();
        float mx = ss[c * 11 + 0];
        #pragma unroll
        for (int oo = 1; oo < OO; oo++) mx = fmaxf(mx, ss[c * 11 + oo]);
        const float e = __expf(s - mx);
        se[c * 11 + o] = e;
        __syncthreads();
        float den = se[c * 11 + 0];
        #pragma unroll
        for (int oo = 1; oo < OO; oo++) den += se[c * 11 + oo];
        const float ap = a * __fdividef(e, den);

        S0 += ap;
        const u64 ap2 = pdup(ap);
        #pragma unroll
        for (int k = 0; k < 8; k++) {
            const u64 t1 = mul2(ap2, v[k]);
            S1[k] = add2(S1[k], t1);
            S2[k] = fma2(t1, v[k], S2[k]);
        }
    }

    // ---- reduce over 32 c's ----------------------------------------------
    #pragma unroll
    for (int off = 16; off > 0; off >>= 1) {
        S0 += __shfl_xor_sync(0xFFFFFFFFu, S0, off);
        #pragma unroll
        for (int k = 0; k < 8; k++) {
            u64 a1 = __shfl_xor_sync(0xFFFFFFFFu, S1[k], off);
            u64 a2 = __shfl_xor_sync(0xFFFFFFFFu, S2[k], off);
            S1[k] = add2(S1[k], a1);
            S2[k] = add2(S2[k], a2);
        }
    }
    if (c == 0) {
        float* dst = g_partials + (size_t)((b * NCH + ch) * OO + o) * 33;
        dst[0] = S0;
        #pragma unroll
        for (int k = 0; k < 8; k++) {
            const int ip = k >> 2, kk = k & 3;
            const int dlo = 8 * ip + kk, dhi = dlo + 4;
            float lo, hi;
            unpack2(S1[k], lo, hi);
            dst[1 + dlo] = lo;  dst[1 + dhi] = hi;
            unpack2(S2[k], lo, hi);
            dst[17 + dlo] = lo; dst[17 + dhi] = hi;
        }
    }

    // ---- winner block per batch does the reduce --------------------------
    __syncthreads();
    if (tid == 0) {
        __threadfence();
        int prev = atomicAdd(&g_count[b], 1);
        *swin = (prev == NCH - 1);
    }
    __syncthreads();
    if (!*swin) return;
    __threadfence();

    if (tid < OO * 16) {
        const int ro = tid >> 4;
        const int rd = tid & 15;

        float R0 = 0.f, R1 = 0.f, R2 = 0.f;
        #pragma unroll 2
        for (int g = 0; g < NCH; g++) {
            const float* p = g_partials + (size_t)((b * NCH + g) * OO + ro) * 33;
            R0 += p[0];
            R1 += p[1 + rd];
            R2 += p[17 + rd];
        }

        const float rs     = R0 + EPSF;
        const float inv_rs = 1.0f / rs;
        const float mu     = R1 * inv_rs;
        const float var    = fmaxf(R2 * inv_rs - mu * mu, 0.0f) + EPSF;
        const float lv     = __logf(var);
        const float ivar   = 1.0f / var;
        const float muinv  = mu * ivar;
        const float mive   = mu * muinv;

        float sumlv = lv, summive = mive;
        #pragma unroll
        for (int off = 1; off < 16; off <<= 1) {
            sumlv   += __shfl_xor_sync(0xFFFFFFFFu, sumlv,   off);
            summive += __shfl_xor_sync(0xFFFFFFFFu, summive, off);
        }

        const float cost = rs * (16.0f * beta_u[ro] + 0.5f * sumlv);
        const float x    = inv_temp * (beta_a[ro] - cost);
        const float actv = 1.0f / (1.0f + __expf(-x));

        if (FINAL) {
            out[(size_t)(b * OO + ro) * 16 + rd] = mu;
            if (rd == 0) out[BB * OO * 16 + b * OO + ro] = actv;
        } else {
            float* pp = g_params + (size_t)(b * OO + ro) * 33;
            pp[1 + rd]  = ivar;
            pp[17 + rd] = muinv;
            if (rd == 0)
                pp[0] = __logf(actv + EPSF)
                      - 0.5f * (16.0f * LOG2PI + sumlv)
                      - 0.5f * summive;
        }
    }
    if (tid == 0) g_count[b] = 0;
}

// ---------------------------------------------------------------------------
extern "C" void kernel_launch(void* const* d_in, const int* in_sizes, int n_in,
                              void* d_out, int out_size)
{
    const float* pose = (const float*)d_in[0];
    const float* act  = (const float*)d_in[1];
    const float* w    = (const float*)d_in[2];
    const float* ba   = (const float*)d_in[3];
    const float* bu   = (const float*)d_in[4];
    float* out = (float*)d_out;

    static int smem_set = 0;
    if (!smem_set) {   // driver state only; not a stream op, capture-safe
        cudaFuncSetAttribute(caps_em<0>, cudaFuncAttributeMaxDynamicSharedMemorySize, SMEM_EM);
        cudaFuncSetAttribute(caps_em<1>, cudaFuncAttributeMaxDynamicSharedMemorySize, SMEM_EM);
        smem_set = 1;
    }

    dim3 g0(PCH, BB);
    dim3 ga(NCH, BB);

    caps_pass0<<<g0, 512>>>(pose, act, w, ba, bu);                        // it=0 (moments)
    caps_em<0><<<ga, TPB, SMEM_EM>>>(pose, act, w, ba, bu, 2.0f, out);    // it=1
    caps_em<1><<<ga, TPB, SMEM_EM>>>(pose, act, w, ba, bu, 3.0f, out);    // it=2 -> out
}